// round 1
// baseline (speedup 1.0000x reference)
#include <cuda_runtime.h>
#include <math.h>

// ---------------- problem constants ----------------
#define BATCH 128
#define CCH   512
#define SS    121      // 11*11
#define SDIM  11
#define KK    9        // 3*3
#define C2    1024     // 2*C
#define CR    32       // C/SIGMA
#define OUT0  (BATCH*CCH*SS)        // 7,929,856 adapted+x
#define TKN   (CCH*SS*KK)           // 557,568 task kernel

// ---------------- scratch (device globals; no allocation) ----------------
__device__ float g_A1[(size_t)BATCH * C2 * SS];   // relu(bn(conv1)) per batch
__device__ float g_asum[C2 * SS];                 // batch-summed relu(bn(conv2))
__device__ float g_tmp[C2 * SS];                  // lo1 output
__device__ float g_task[CCH * SS];                // task_s
__device__ float g_sk[BATCH * SS * KK];           // spatial kernel (x)
__device__ float g_skt[SS * KK];                  // spatial kernel (task_s)
__device__ float g_y[BATCH * CCH];                // dct pooled (x)
__device__ float g_yt[CCH];                       // dct pooled (task_s)
__device__ float g_ck[(size_t)BATCH * CCH * KK];  // channel kernel (x)
__device__ float g_ckt[CCH * KK];                 // channel kernel (task_s)

// ---------------- tiled SGEMM with fused BN epilogue ----------------
// O[o][p] = act( (sum_c W[o][c]*X[c][p] + bias[o]) * gamma[o]/sqrt(1+eps) + beta[o] )
// tile: 64 rows x 128 cols, 256 threads, 4x8 per-thread register tile.
// mode 0: relu store; mode 1: relu atomicAdd (batch reduce); mode 2: sigmoid store
__global__ __launch_bounds__(256) void gemm_fused(
    const float* __restrict__ W, const float* __restrict__ X,
    const float* __restrict__ bias, const float* __restrict__ gamma,
    const float* __restrict__ beta, float* __restrict__ out,
    int M, int Kd, int P, long long strideX, long long strideO, int mode)
{
    __shared__ float Ws[16][64];
    __shared__ float Xs[16][128];

    const int b = blockIdx.z;
    const float* Xb = X + (long long)b * strideX;
    float* Ob = out + (long long)b * strideO;
    const int row0 = blockIdx.y * 64;
    const int tid = threadIdx.x;
    const int tr = tid >> 4;      // 0..15
    const int tc = tid & 15;      // 0..15

    float acc[4][8];
#pragma unroll
    for (int i = 0; i < 4; i++)
#pragma unroll
        for (int j = 0; j < 8; j++) acc[i][j] = 0.f;

    for (int k0 = 0; k0 < Kd; k0 += 16) {
        // load W tile (64x16) transposed into Ws[k][r]
#pragma unroll
        for (int i = 0; i < 4; i++) {
            int idx = tid + i * 256;
            int r = idx >> 4, kk = idx & 15;
            Ws[kk][r] = W[(long long)(row0 + r) * Kd + k0 + kk];
        }
        // load X tile (16x128), zero-pad p >= P
#pragma unroll
        for (int i = 0; i < 8; i++) {
            int idx = tid + i * 256;
            int kk = idx >> 7, p = idx & 127;
            Xs[kk][p] = (p < P) ? Xb[(long long)(k0 + kk) * P + p] : 0.f;
        }
        __syncthreads();
#pragma unroll
        for (int kk = 0; kk < 16; kk++) {
            float4 a = *(const float4*)&Ws[kk][tr * 4];
            float4 b0 = *(const float4*)&Xs[kk][tc * 8];
            float4 b1 = *(const float4*)&Xs[kk][tc * 8 + 4];
            float av[4] = {a.x, a.y, a.z, a.w};
            float bv[8] = {b0.x, b0.y, b0.z, b0.w, b1.x, b1.y, b1.z, b1.w};
#pragma unroll
            for (int i = 0; i < 4; i++)
#pragma unroll
                for (int j = 0; j < 8; j++) acc[i][j] = fmaf(av[i], bv[j], acc[i][j]);
        }
        __syncthreads();
    }

    const float rs = rsqrtf(1.f + 1e-5f);
#pragma unroll
    for (int i = 0; i < 4; i++) {
        int r = row0 + tr * 4 + i;
        float sc = gamma[r] * rs, sh = beta[r], bi = bias[r];
#pragma unroll
        for (int j = 0; j < 8; j++) {
            int p = tc * 8 + j;
            if (p < P) {
                float v = (acc[i][j] + bi) * sc + sh;
                if (mode == 0) {
                    Ob[(long long)r * P + p] = fmaxf(v, 0.f);
                } else if (mode == 1) {
                    atomicAdd(&Ob[(long long)r * P + p], fmaxf(v, 0.f));
                } else {
                    Ob[(long long)r * P + p] = 1.f / (1.f + expf(-v));
                }
            }
        }
    }
}

// ---------------- zero fill ----------------
__global__ void zero_k(float* p, int n) {
    int i = blockIdx.x * 256 + threadIdx.x;
    if (i < n) p[i] = 0.f;
}

// ---------------- spatial kernel: sk[b][p][kk] ----------------
// sk = (sum_c f[b,c,p]*w_conv[kk,c] + b_conv[kk]) * g_sp[p]/sqrt(1+eps) + b_sp[p]
__global__ __launch_bounds__(128) void spatial_k(
    const float* __restrict__ f, const float* __restrict__ w_conv,
    const float* __restrict__ b_conv, const float* __restrict__ g_sp,
    const float* __restrict__ b_sp, float* __restrict__ out)
{
    __shared__ float wc[KK * CCH];
    const int b = blockIdx.x;
    const int tid = threadIdx.x;
    for (int i = tid; i < KK * CCH; i += 128) wc[i] = w_conv[i];
    __syncthreads();
    if (tid < SS) {
        float acc[KK];
#pragma unroll
        for (int k = 0; k < KK; k++) acc[k] = 0.f;
        const float* fb = f + (long long)b * CCH * SS;
        for (int c = 0; c < CCH; c++) {
            float xv = fb[c * SS + tid];
#pragma unroll
            for (int k = 0; k < KK; k++) acc[k] = fmaf(xv, wc[k * CCH + c], acc[k]);
        }
        float gs = g_sp[tid] * rsqrtf(1.f + 1e-5f);
        float bs = b_sp[tid];
#pragma unroll
        for (int k = 0; k < KK; k++)
            out[(long long)b * SS * KK + tid * KK + k] = (acc[k] + b_conv[k]) * gs + bs;
    }
}

// ---------------- DCT pooling: y[b][c] = sum_p f[b,c,p]*dct[c,p] ----------------
__global__ __launch_bounds__(128) void dct_pool(
    const float* __restrict__ f, const float* __restrict__ dct, float* __restrict__ y)
{
    const int b = blockIdx.y;
    const int c = blockIdx.x * 4 + (threadIdx.x >> 5);
    const int lane = threadIdx.x & 31;
    const float* fb = f + ((long long)b * CCH + c) * SS;
    const float* dc = dct + (long long)c * SS;
    float s = 0.f;
    for (int p = lane; p < SS; p += 32) s = fmaf(fb[p], dc[p], s);
#pragma unroll
    for (int o = 16; o > 0; o >>= 1) s += __shfl_xor_sync(0xffffffffu, s, o);
    if (lane == 0) y[(long long)b * CCH + c] = s;
}

// ---------------- channel-attention MLP: ck[b][c][kk] ----------------
__global__ __launch_bounds__(256) void mlp_k(
    const float* __restrict__ y, const float* __restrict__ fc1,
    const float* __restrict__ fc2, const float* __restrict__ g_ch,
    const float* __restrict__ b_ch, float* __restrict__ ck)
{
    __shared__ float ys[CCH];
    __shared__ float hs[CR];
    const int b = blockIdx.x;
    const int tid = threadIdx.x;
    for (int i = tid; i < CCH; i += 256) ys[i] = y[(long long)b * CCH + i];
    __syncthreads();
    if (tid < CR) {
        const float* r = fc1 + tid * CCH;
        float s = 0.f;
        for (int c = 0; c < CCH; c++) s = fmaf(ys[c], r[c], s);
        hs[tid] = fmaxf(s, 0.f);
    }
    __syncthreads();
    const float rs = rsqrtf(1.f + 1e-5f);
    for (int m = tid; m < CCH * KK; m += 256) {
        const float* r = fc2 + m * CR;
        float s = 0.f;
#pragma unroll
        for (int j = 0; j < CR; j++) s = fmaf(hs[j], r[j], s);
        s = 1.f / (1.f + expf(-s));
        int c = m / KK;
        ck[(long long)b * CCH * KK + m] = s * g_ch[c] * rs + b_ch[c];
    }
}

// ---------------- task kernel writer: tk[c][p][kk] = sk_t[p,kk]*ck_t[c,kk] ----------------
__global__ __launch_bounds__(128) void tk_writer(
    const float* __restrict__ skt, const float* __restrict__ ckt, float* __restrict__ tk)
{
    const int c = blockIdx.x;
    for (int i = threadIdx.x; i < SS * KK; i += 128) {
        int kk = i % KK;
        tk[(long long)c * SS * KK + i] = skt[i] * ckt[c * KK + kk];
    }
}

// ---------------- final: adapted + x ----------------
__global__ __launch_bounds__(128) void final_k(
    const float* __restrict__ x, const float* __restrict__ sk,
    const float* __restrict__ ck, const float* __restrict__ tk,
    float* __restrict__ out)
{
    __shared__ float xs[13 * 13];
    __shared__ float sks[SS * KK];
    const int c = blockIdx.x, b = blockIdx.y;
    const int tid = threadIdx.x;

    for (int i = tid; i < 169; i += 128) xs[i] = 0.f;
    for (int i = tid; i < SS * KK; i += 128) sks[i] = sk[(long long)b * SS * KK + i];
    __syncthreads();
    const float* xb = x + ((long long)b * CCH + c) * SS;
    for (int i = tid; i < SS; i += 128) {
        int h = i / SDIM, w = i % SDIM;
        xs[(h + 1) * 13 + (w + 1)] = xb[i];
    }
    __syncthreads();

    float ckv[KK];
#pragma unroll
    for (int k = 0; k < KK; k++) ckv[k] = ck[((long long)b * CCH + c) * KK + k];

    const float* tkc = tk + (long long)c * SS * KK;
    const int p = tid;
    if (p < SS) {
        int h = p / SDIM, w = p % SDIM;
        float acc = 0.f;
#pragma unroll
        for (int k = 0; k < KK; k++) {
            int ki = k / 3, kj = k % 3;
            float xv = xs[(h + ki) * 13 + (w + kj)];
            acc = fmaf(xv, tkc[p * KK + k] * sks[p * KK + k] * ckv[k], acc);
        }
        out[((long long)b * CCH + c) * SS + p] = acc * (1.f / 9.f) + xb[p];
    }
}

// ---------------- launch ----------------
extern "C" void kernel_launch(void* const* d_in, const int* in_sizes, int n_in,
                              void* d_out, int out_size)
{
    const float* x      = (const float*)d_in[0];
    const float* dct_w  = (const float*)d_in[1];
    const float* w_conv = (const float*)d_in[2];
    const float* b_conv = (const float*)d_in[3];
    const float* g_sp   = (const float*)d_in[4];
    const float* b_sp   = (const float*)d_in[5];
    const float* g_ch   = (const float*)d_in[6];
    const float* b_ch   = (const float*)d_in[7];
    const float* fc1    = (const float*)d_in[8];
    const float* fc2    = (const float*)d_in[9];
    const float* up_w1  = (const float*)d_in[10];
    const float* up_b1  = (const float*)d_in[11];
    const float* up_g1  = (const float*)d_in[12];
    const float* up_bb1 = (const float*)d_in[13];
    const float* up_w2  = (const float*)d_in[14];
    const float* up_b2  = (const float*)d_in[15];
    const float* up_g2  = (const float*)d_in[16];
    const float* up_bb2 = (const float*)d_in[17];
    const float* lo_w1  = (const float*)d_in[18];
    const float* lo_b1  = (const float*)d_in[19];
    const float* lo_g1  = (const float*)d_in[20];
    const float* lo_bb1 = (const float*)d_in[21];
    const float* lo_w2  = (const float*)d_in[22];
    const float* lo_b2  = (const float*)d_in[23];
    const float* lo_g2  = (const float*)d_in[24];
    const float* lo_bb2 = (const float*)d_in[25];

    float *A1, *asum, *tmp, *task, *sk, *skt, *y, *yt, *ck, *ckt;
    cudaGetSymbolAddress((void**)&A1,   g_A1);
    cudaGetSymbolAddress((void**)&asum, g_asum);
    cudaGetSymbolAddress((void**)&tmp,  g_tmp);
    cudaGetSymbolAddress((void**)&task, g_task);
    cudaGetSymbolAddress((void**)&sk,   g_sk);
    cudaGetSymbolAddress((void**)&skt,  g_skt);
    cudaGetSymbolAddress((void**)&y,    g_y);
    cudaGetSymbolAddress((void**)&yt,   g_yt);
    cudaGetSymbolAddress((void**)&ck,   g_ck);
    cudaGetSymbolAddress((void**)&ckt,  g_ckt);

    float* out = (float*)d_out;
    float* tk  = out + OUT0;

    // CLM task path
    gemm_fused<<<dim3(1, C2 / 64, BATCH), 256>>>(up_w1, x, up_b1, up_g1, up_bb1,
        A1, C2, CCH, SS, (long long)CCH * SS, (long long)C2 * SS, 0);
    zero_k<<<(C2 * SS + 255) / 256, 256>>>(asum, C2 * SS);
    gemm_fused<<<dim3(1, C2 / 64, BATCH), 256>>>(up_w2, A1, up_b2, up_g2, up_bb2,
        asum, C2, C2, SS, (long long)C2 * SS, 0, 1);
    gemm_fused<<<dim3(1, C2 / 64, 1), 256>>>(lo_w1, asum, lo_b1, lo_g1, lo_bb1,
        tmp, C2, C2, SS, 0, 0, 0);
    gemm_fused<<<dim3(1, CCH / 64, 1), 256>>>(lo_w2, tmp, lo_b2, lo_g2, lo_bb2,
        task, CCH, C2, SS, 0, 0, 2);

    // instance + task spatial/channel kernels
    spatial_k<<<BATCH, 128>>>(x, w_conv, b_conv, g_sp, b_sp, sk);
    spatial_k<<<1, 128>>>(task, w_conv, b_conv, g_sp, b_sp, skt);
    dct_pool<<<dim3(CCH / 4, BATCH), 128>>>(x, dct_w, y);
    dct_pool<<<dim3(CCH / 4, 1), 128>>>(task, dct_w, yt);
    mlp_k<<<BATCH, 256>>>(y, fc1, fc2, g_ch, b_ch, ck);
    mlp_k<<<1, 256>>>(yt, fc1, fc2, g_ch, b_ch, ckt);

    // outputs
    tk_writer<<<CCH, 128>>>(skt, ckt, tk);
    final_k<<<dim3(CCH, BATCH), 128>>>(x, sk, ck, tk, out);
}

// round 2
// speedup vs baseline: 1.5815x; 1.5815x over previous
#include <cuda_runtime.h>
#include <math.h>

// ---------------- problem constants ----------------
#define BATCH 128
#define CCH   512
#define SS    121      // 11*11
#define SDIM  11
#define KK    9        // 3*3
#define C2    1024     // 2*C
#define CR    32       // C/SIGMA
#define OUT0  (BATCH*CCH*SS)

// ---------------- scratch (device globals; no allocation) ----------------
__device__ float g_A1[(size_t)BATCH * C2 * SS];   // relu(bn(conv1)) per batch
__device__ float g_asum[C2 * SS];                 // batch-summed relu(bn(conv2))
__device__ float g_acc1[C2 * SS];                 // lo1 split-K raw accumulator
__device__ float g_acc2[CCH * SS];                // lo2 split-K raw accumulator
__device__ float g_tmp[C2 * SS];                  // lo1 output (post BN+relu)
__device__ float g_task[CCH * SS];                // task_s
__device__ float g_sk[BATCH * SS * KK];
__device__ float g_skt[SS * KK];
__device__ float g_y[BATCH * CCH];
__device__ float g_yt[CCH];
__device__ float g_ck[(size_t)BATCH * CCH * KK];
__device__ float g_ckt[CCH * KK];

// ================= 128x128 tiled SGEMM, 8x8 thread tile, double-buffered =================
// O[o][p] = act( (sum_c W[o][c]*X[c][p] + bias[o]) * gamma[o]/sqrt(1+eps) + beta[o] )
// mode 0: BN+relu store; mode 1: BN+relu atomicAdd; mode 2: BN+sigmoid store;
// mode 3: raw atomicAdd (split-K partial, no BN)
#define BM 128
#define BN_ 128
#define BK 8

__global__ __launch_bounds__(256, 2) void gemm128(
    const float* __restrict__ W, const float* __restrict__ X,
    const float* __restrict__ bias, const float* __restrict__ gamma,
    const float* __restrict__ beta, float* __restrict__ out,
    int Kd, int P, int kchunk, long long strideX, long long strideO, int mode)
{
    __shared__ __align__(16) float Ws[2][BK][BM + 4];
    __shared__ __align__(16) float Xs[2][BK][BN_];

    const int b = blockIdx.z;
    const float* Xb = X + (long long)b * strideX;
    float* Ob = out + (long long)b * strideO;
    const int row0 = blockIdx.y * BM;
    const int k_begin = blockIdx.x * kchunk;

    const int tid = threadIdx.x;
    const int warp = tid >> 5, lane = tid & 31;
    const int wr = warp & 3, wc = warp >> 2;   // 4x2 warp grid
    const int lr = lane & 3, lc = lane >> 2;   // 4x8 lane grid
    const int tm = wr * 32 + lr * 8;           // thread row base (0..120)
    const int tn = wc * 64 + lc * 8;           // thread col base (0..120)

    // W tile loader: thread -> (row wm, k-offset wk), one float4
    const int wm = tid >> 1;
    const int wk = (tid & 1) * 4;

    float acc[8][8] = {};

    const int nt = kchunk / BK;

    // prologue: load tile 0 into buffer 0
    {
        float4 w4 = *(const float4*)&W[(long long)(row0 + wm) * Kd + k_begin + wk];
        Ws[0][wk + 0][wm] = w4.x; Ws[0][wk + 1][wm] = w4.y;
        Ws[0][wk + 2][wm] = w4.z; Ws[0][wk + 3][wm] = w4.w;
#pragma unroll
        for (int i = 0; i < 4; i++) {
            int idx = tid + i * 256;
            int kk = idx >> 7, p = idx & 127;
            Xs[0][kk][p] = (p < P) ? Xb[(long long)(k_begin + kk) * P + p] : 0.f;
        }
    }
    __syncthreads();

    for (int t = 0; t < nt; t++) {
        const int cur = t & 1;
        float4 w4;
        float x4[4];
        const bool has_next = (t + 1 < nt);
        if (has_next) {
            int k1 = k_begin + (t + 1) * BK;
            w4 = *(const float4*)&W[(long long)(row0 + wm) * Kd + k1 + wk];
#pragma unroll
            for (int i = 0; i < 4; i++) {
                int idx = tid + i * 256;
                int kk = idx >> 7, p = idx & 127;
                x4[i] = (p < P) ? Xb[(long long)(k1 + kk) * P + p] : 0.f;
            }
        }
#pragma unroll
        for (int kk = 0; kk < BK; kk++) {
            float a[8], bb[8];
            *(float4*)&a[0]  = *(const float4*)&Ws[cur][kk][tm];
            *(float4*)&a[4]  = *(const float4*)&Ws[cur][kk][tm + 4];
            *(float4*)&bb[0] = *(const float4*)&Xs[cur][kk][tn];
            *(float4*)&bb[4] = *(const float4*)&Xs[cur][kk][tn + 4];
#pragma unroll
            for (int i = 0; i < 8; i++)
#pragma unroll
                for (int j = 0; j < 8; j++)
                    acc[i][j] = fmaf(a[i], bb[j], acc[i][j]);
        }
        if (has_next) {
            const int nb = cur ^ 1;
            Ws[nb][wk + 0][wm] = w4.x; Ws[nb][wk + 1][wm] = w4.y;
            Ws[nb][wk + 2][wm] = w4.z; Ws[nb][wk + 3][wm] = w4.w;
#pragma unroll
            for (int i = 0; i < 4; i++) {
                int idx = tid + i * 256;
                int kk = idx >> 7, p = idx & 127;
                Xs[nb][kk][p] = x4[i];
            }
            __syncthreads();
        }
    }

    if (mode == 3) {
#pragma unroll
        for (int i = 0; i < 8; i++) {
            int r = row0 + tm + i;
#pragma unroll
            for (int j = 0; j < 8; j++) {
                int p = tn + j;
                if (p < P) atomicAdd(&Ob[(long long)r * P + p], acc[i][j]);
            }
        }
    } else {
        const float rs = rsqrtf(1.f + 1e-5f);
#pragma unroll
        for (int i = 0; i < 8; i++) {
            int r = row0 + tm + i;
            float sc = gamma[r] * rs, sh = beta[r], bi = bias[r];
#pragma unroll
            for (int j = 0; j < 8; j++) {
                int p = tn + j;
                if (p < P) {
                    float v = (acc[i][j] + bi) * sc + sh;
                    if (mode == 0) {
                        Ob[(long long)r * P + p] = fmaxf(v, 0.f);
                    } else if (mode == 1) {
                        atomicAdd(&Ob[(long long)r * P + p], fmaxf(v, 0.f));
                    } else {
                        Ob[(long long)r * P + p] = 1.f / (1.f + expf(-v));
                    }
                }
            }
        }
    }
}

// ---------------- zero fill ----------------
__global__ void zero_k(float* p, int n) {
    int i = blockIdx.x * 256 + threadIdx.x;
    if (i < n) p[i] = 0.f;
}

// ---------------- split-K epilogue: BN + act ----------------
// mode 0: relu, mode 1: sigmoid
__global__ void epi_bn(const float* __restrict__ acc, const float* __restrict__ bias,
                       const float* __restrict__ gamma, const float* __restrict__ beta,
                       float* __restrict__ out, int P, int n, int mode)
{
    int i = blockIdx.x * 256 + threadIdx.x;
    if (i < n) {
        int r = i / P;
        float v = (acc[i] + bias[r]) * gamma[r] * rsqrtf(1.f + 1e-5f) + beta[r];
        out[i] = mode ? (1.f / (1.f + expf(-v))) : fmaxf(v, 0.f);
    }
}

// ---------------- spatial kernel: sk[b][p][kk] ----------------
__global__ __launch_bounds__(128) void spatial_k(
    const float* __restrict__ f, const float* __restrict__ w_conv,
    const float* __restrict__ b_conv, const float* __restrict__ g_sp,
    const float* __restrict__ b_sp, float* __restrict__ out)
{
    __shared__ float wc[KK * CCH];
    const int b = blockIdx.x;
    const int tid = threadIdx.x;
    for (int i = tid; i < KK * CCH; i += 128) wc[i] = w_conv[i];
    __syncthreads();
    if (tid < SS) {
        float acc[KK];
#pragma unroll
        for (int k = 0; k < KK; k++) acc[k] = 0.f;
        const float* fb = f + (long long)b * CCH * SS;
        for (int c = 0; c < CCH; c++) {
            float xv = fb[c * SS + tid];
#pragma unroll
            for (int k = 0; k < KK; k++) acc[k] = fmaf(xv, wc[k * CCH + c], acc[k]);
        }
        float gs = g_sp[tid] * rsqrtf(1.f + 1e-5f);
        float bs = b_sp[tid];
#pragma unroll
        for (int k = 0; k < KK; k++)
            out[(long long)b * SS * KK + tid * KK + k] = (acc[k] + b_conv[k]) * gs + bs;
    }
}

// ---------------- DCT pooling ----------------
__global__ __launch_bounds__(128) void dct_pool(
    const float* __restrict__ f, const float* __restrict__ dct, float* __restrict__ y)
{
    const int b = blockIdx.y;
    const int c = blockIdx.x * 4 + (threadIdx.x >> 5);
    const int lane = threadIdx.x & 31;
    const float* fb = f + ((long long)b * CCH + c) * SS;
    const float* dc = dct + (long long)c * SS;
    float s = 0.f;
    for (int p = lane; p < SS; p += 32) s = fmaf(fb[p], dc[p], s);
#pragma unroll
    for (int o = 16; o > 0; o >>= 1) s += __shfl_xor_sync(0xffffffffu, s, o);
    if (lane == 0) y[(long long)b * CCH + c] = s;
}

// ---------------- channel-attention MLP ----------------
__global__ __launch_bounds__(256) void mlp_k(
    const float* __restrict__ y, const float* __restrict__ fc1,
    const float* __restrict__ fc2, const float* __restrict__ g_ch,
    const float* __restrict__ b_ch, float* __restrict__ ck)
{
    __shared__ float ys[CCH];
    __shared__ float hs[CR];
    const int b = blockIdx.x;
    const int tid = threadIdx.x;
    for (int i = tid; i < CCH; i += 256) ys[i] = y[(long long)b * CCH + i];
    __syncthreads();
    if (tid < CR) {
        const float* r = fc1 + tid * CCH;
        float s = 0.f;
        for (int c = 0; c < CCH; c++) s = fmaf(ys[c], r[c], s);
        hs[tid] = fmaxf(s, 0.f);
    }
    __syncthreads();
    const float rs = rsqrtf(1.f + 1e-5f);
    for (int m = tid; m < CCH * KK; m += 256) {
        const float* r = fc2 + m * CR;
        float s = 0.f;
#pragma unroll
        for (int j = 0; j < CR; j++) s = fmaf(hs[j], r[j], s);
        s = 1.f / (1.f + expf(-s));
        int c = m / KK;
        ck[(long long)b * CCH * KK + m] = s * g_ch[c] * rs + b_ch[c];
    }
}

// ---------------- task kernel writer ----------------
__global__ __launch_bounds__(128) void tk_writer(
    const float* __restrict__ skt, const float* __restrict__ ckt, float* __restrict__ tk)
{
    const int c = blockIdx.x;
    for (int i = threadIdx.x; i < SS * KK; i += 128) {
        int kk = i % KK;
        tk[(long long)c * SS * KK + i] = skt[i] * ckt[c * KK + kk];
    }
}

// ---------------- final: adapted + x ----------------
__global__ __launch_bounds__(128) void final_k(
    const float* __restrict__ x, const float* __restrict__ sk,
    const float* __restrict__ ck, const float* __restrict__ tk,
    float* __restrict__ out)
{
    __shared__ float xs[13 * 13];
    __shared__ float sks[SS * KK];
    const int c = blockIdx.x, b = blockIdx.y;
    const int tid = threadIdx.x;

    for (int i = tid; i < 169; i += 128) xs[i] = 0.f;
    for (int i = tid; i < SS * KK; i += 128) sks[i] = sk[(long long)b * SS * KK + i];
    __syncthreads();
    const float* xb = x + ((long long)b * CCH + c) * SS;
    for (int i = tid; i < SS; i += 128) {
        int h = i / SDIM, w = i % SDIM;
        xs[(h + 1) * 13 + (w + 1)] = xb[i];
    }
    __syncthreads();

    float ckv[KK];
#pragma unroll
    for (int k = 0; k < KK; k++) ckv[k] = ck[((long long)b * CCH + c) * KK + k];

    const float* tkc = tk + (long long)c * SS * KK;
    const int p = tid;
    if (p < SS) {
        int h = p / SDIM, w = p % SDIM;
        float acc = 0.f;
#pragma unroll
        for (int k = 0; k < KK; k++) {
            int ki = k / 3, kj = k % 3;
            float xv = xs[(h + ki) * 13 + (w + kj)];
            acc = fmaf(xv, tkc[p * KK + k] * sks[p * KK + k] * ckv[k], acc);
        }
        out[((long long)b * CCH + c) * SS + p] = acc * (1.f / 9.f) + xb[p];
    }
}

// ---------------- launch ----------------
extern "C" void kernel_launch(void* const* d_in, const int* in_sizes, int n_in,
                              void* d_out, int out_size)
{
    const float* x      = (const float*)d_in[0];
    const float* dct_w  = (const float*)d_in[1];
    const float* w_conv = (const float*)d_in[2];
    const float* b_conv = (const float*)d_in[3];
    const float* g_sp   = (const float*)d_in[4];
    const float* b_sp   = (const float*)d_in[5];
    const float* g_ch   = (const float*)d_in[6];
    const float* b_ch   = (const float*)d_in[7];
    const float* fc1    = (const float*)d_in[8];
    const float* fc2    = (const float*)d_in[9];
    const float* up_w1  = (const float*)d_in[10];
    const float* up_b1  = (const float*)d_in[11];
    const float* up_g1  = (const float*)d_in[12];
    const float* up_bb1 = (const float*)d_in[13];
    const float* up_w2  = (const float*)d_in[14];
    const float* up_b2  = (const float*)d_in[15];
    const float* up_g2  = (const float*)d_in[16];
    const float* up_bb2 = (const float*)d_in[17];
    const float* lo_w1  = (const float*)d_in[18];
    const float* lo_b1  = (const float*)d_in[19];
    const float* lo_g1  = (const float*)d_in[20];
    const float* lo_bb1 = (const float*)d_in[21];
    const float* lo_w2  = (const float*)d_in[22];
    const float* lo_b2  = (const float*)d_in[23];
    const float* lo_g2  = (const float*)d_in[24];
    const float* lo_bb2 = (const float*)d_in[25];

    float *A1, *asum, *acc1, *acc2, *tmp, *task, *sk, *skt, *y, *yt, *ck, *ckt;
    cudaGetSymbolAddress((void**)&A1,   g_A1);
    cudaGetSymbolAddress((void**)&asum, g_asum);
    cudaGetSymbolAddress((void**)&acc1, g_acc1);
    cudaGetSymbolAddress((void**)&acc2, g_acc2);
    cudaGetSymbolAddress((void**)&tmp,  g_tmp);
    cudaGetSymbolAddress((void**)&task, g_task);
    cudaGetSymbolAddress((void**)&sk,   g_sk);
    cudaGetSymbolAddress((void**)&skt,  g_skt);
    cudaGetSymbolAddress((void**)&y,    g_y);
    cudaGetSymbolAddress((void**)&yt,   g_yt);
    cudaGetSymbolAddress((void**)&ck,   g_ck);
    cudaGetSymbolAddress((void**)&ckt,  g_ckt);

    float* out = (float*)d_out;
    float* tk  = out + OUT0;

    // zero accumulators up front
    zero_k<<<(C2 * SS + 255) / 256, 256>>>(asum, C2 * SS);
    zero_k<<<(C2 * SS + 255) / 256, 256>>>(acc1, C2 * SS);
    zero_k<<<(CCH * SS + 255) / 256, 256>>>(acc2, CCH * SS);

    // instance-path small kernels (independent of GEMM chain)
    spatial_k<<<BATCH, 128>>>(x, w_conv, b_conv, g_sp, b_sp, sk);
    dct_pool<<<dim3(CCH / 4, BATCH), 128>>>(x, dct_w, y);
    mlp_k<<<BATCH, 256>>>(y, fc1, fc2, g_ch, b_ch, ck);

    // CLM task path
    // GEMM1: A1 = relu(bn(up_w1 @ x))   [per batch]
    gemm128<<<dim3(1, C2 / BM, BATCH), 256>>>(up_w1, x, up_b1, up_g1, up_bb1,
        A1, CCH, SS, CCH, (long long)CCH * SS, (long long)C2 * SS, 0);
    // GEMM2: asum += relu(bn(up_w2 @ A1))  [fused batch-sum]
    gemm128<<<dim3(1, C2 / BM, BATCH), 256>>>(up_w2, A1, up_b2, up_g2, up_bb2,
        asum, C2, SS, C2, (long long)C2 * SS, 0, 1);
    // lo1: split-K raw partials, then BN+relu epilogue
    gemm128<<<dim3(16, C2 / BM, 1), 256>>>(lo_w1, asum, lo_b1, lo_g1, lo_bb1,
        acc1, C2, SS, C2 / 16, 0, 0, 3);
    epi_bn<<<(C2 * SS + 255) / 256, 256>>>(acc1, lo_b1, lo_g1, lo_bb1, tmp, SS, C2 * SS, 0);
    // lo2: split-K raw partials, then BN+sigmoid epilogue
    gemm128<<<dim3(16, CCH / BM, 1), 256>>>(lo_w2, tmp, lo_b2, lo_g2, lo_bb2,
        acc2, C2, SS, C2 / 16, 0, 0, 3);
    epi_bn<<<(CCH * SS + 255) / 256, 256>>>(acc2, lo_b2, lo_g2, lo_bb2, task, SS, CCH * SS, 1);

    // task-path small kernels
    spatial_k<<<1, 128>>>(task, w_conv, b_conv, g_sp, b_sp, skt);
    dct_pool<<<dim3(CCH / 4, 1), 128>>>(task, dct_w, yt);
    mlp_k<<<1, 256>>>(yt, fc1, fc2, g_ch, b_ch, ckt);

    // outputs
    tk_writer<<<CCH, 128>>>(skt, ckt, tk);
    final_k<<<dim3(CCH, BATCH), 128>>>(x, sk, ck, tk, out);
}